// round 2
// baseline (speedup 1.0000x reference)
#include <cuda_runtime.h>
#include <cuda_bf16.h>
#include <math.h>

#define TOKENS 4096
#define DM     1024
#define DFF    4096
#define HEADS  16
#define DK     64
#define SEQ    2048
#define BATCH  2

// ---------------- scratch (device globals: no allocation) ----------------
__device__ float g_Q[TOKENS * DM];
__device__ float g_K[TOKENS * DM];
__device__ float g_V[TOKENS * DM];
__device__ float g_CTX[TOKENS * DM];
__device__ float g_T1[TOKENS * DM];   // pre-layernorm buffer (reused)
__device__ float g_AO[TOKENS * DM];   // attn_out (post LN1)
__device__ float g_H[TOKENS * DFF];   // FF hidden

__device__ __forceinline__ float gelu_exact(float x) {
    return 0.5f * x * (1.0f + erff(x * 0.70710678118654752f));
}

// ---------------- generic SGEMM: C = A[M,K] @ B[K,N] + bias (+R) (+gelu) --
// EPI: 0 = bias only, 1 = bias + gelu, 2 = bias + residual
template <int EPI>
__global__ __launch_bounds__(256) void gemm_kernel(
    const float* __restrict__ A, const float* __restrict__ B,
    const float* __restrict__ bias, const float* __restrict__ R,
    float* __restrict__ C, int M, int N, int K)
{
    const int BM = 128, BN = 128, BK = 16;
    __shared__ float As[BK][BM];
    __shared__ float Bs[BK][BN];

    int tid = threadIdx.x;
    int tx = tid & 15;        // 0..15 -> 8 cols each
    int ty = tid >> 4;        // 0..15 -> 8 rows each
    int rowBase = blockIdx.y * BM;
    int colBase = blockIdx.x * BN;

    float acc[8][8];
#pragma unroll
    for (int i = 0; i < 8; i++)
#pragma unroll
        for (int j = 0; j < 8; j++) acc[i][j] = 0.0f;

    for (int k0 = 0; k0 < K; k0 += BK) {
        // load A tile (128x16) as 512 float4, store transposed As[k][m]
#pragma unroll
        for (int i = 0; i < 2; i++) {
            int s = tid + i * 256;
            int r = s >> 2;
            int c4 = (s & 3) * 4;
            float4 a = *(const float4*)&A[(size_t)(rowBase + r) * K + k0 + c4];
            As[c4 + 0][r] = a.x;
            As[c4 + 1][r] = a.y;
            As[c4 + 2][r] = a.z;
            As[c4 + 3][r] = a.w;
        }
        // load B tile (16x128) as 512 float4
#pragma unroll
        for (int i = 0; i < 2; i++) {
            int s = tid + i * 256;
            int r = s >> 5;
            int c4 = (s & 31) * 4;
            *(float4*)&Bs[r][c4] = *(const float4*)&B[(size_t)(k0 + r) * N + colBase + c4];
        }
        __syncthreads();

#pragma unroll
        for (int k = 0; k < BK; k++) {
            float ra[8], rb[8];
            *(float4*)&ra[0] = *(float4*)&As[k][ty * 8];
            *(float4*)&ra[4] = *(float4*)&As[k][ty * 8 + 4];
            *(float4*)&rb[0] = *(float4*)&Bs[k][tx * 8];
            *(float4*)&rb[4] = *(float4*)&Bs[k][tx * 8 + 4];
#pragma unroll
            for (int i = 0; i < 8; i++)
#pragma unroll
                for (int j = 0; j < 8; j++)
                    acc[i][j] = fmaf(ra[i], rb[j], acc[i][j]);
        }
        __syncthreads();
    }

    // epilogue
#pragma unroll
    for (int j = 0; j < 8; j += 4) {
        int col = colBase + tx * 8 + j;
        float4 bz = *(const float4*)&bias[col];
#pragma unroll
        for (int i = 0; i < 8; i++) {
            int row = rowBase + ty * 8 + i;
            float4 v;
            v.x = acc[i][j + 0] + bz.x;
            v.y = acc[i][j + 1] + bz.y;
            v.z = acc[i][j + 2] + bz.z;
            v.w = acc[i][j + 3] + bz.w;
            if (EPI == 2) {
                float4 rv = *(const float4*)&R[(size_t)row * N + col];
                v.x += rv.x; v.y += rv.y; v.z += rv.z; v.w += rv.w;
            }
            if (EPI == 1) {
                v.x = gelu_exact(v.x);
                v.y = gelu_exact(v.y);
                v.z = gelu_exact(v.z);
                v.w = gelu_exact(v.w);
            }
            *(float4*)&C[(size_t)row * N + col] = v;
        }
    }
}

// ---------------- flash attention (fp32, online softmax) -----------------
// block: 256 threads; one block per (q_tile=64 rows, head, batch)
// thread t: row r = t/4, group c = t%4.
//   S phase: owns columns j = c + 4*jj (jj 0..15)   [conflict-free Ks reads]
//   O phase: owns dims    d = c*16 + jj             [float4 Vs reads/stores]
__global__ __launch_bounds__(256) void attn_kernel(
    const float* __restrict__ Q, const float* __restrict__ K,
    const float* __restrict__ V, const unsigned char* __restrict__ mask,
    float* __restrict__ CTX)
{
    const int P = 68;  // smem row pitch (floats), 16B-aligned rows
    extern __shared__ float sm[];
    float* Qs = sm;                // 64 * P
    float* Ks = sm + 64 * P;
    float* Vs = sm + 2 * 64 * P;
    float* Ps = sm + 3 * 64 * P;

    int tid = threadIdx.x;
    int c = tid & 3;
    int r = tid >> 2;
    int q0 = blockIdx.x * 64;
    int h  = blockIdx.y;
    int b  = blockIdx.z;
    const float scale = 0.125f;  // 1/sqrt(64)

    // load Q tile (64 x 64) into smem
    const float* Qbase = Q + ((size_t)(b * SEQ + q0)) * DM + h * DK;
#pragma unroll
    for (int i = 0; i < 4; i++) {
        int s = tid + i * 256;
        int rr = s >> 4;
        int c4 = (s & 15) * 4;
        *(float4*)&Qs[rr * P + c4] = *(const float4*)&Qbase[(size_t)rr * DM + c4];
    }

    float o[16];
#pragma unroll
    for (int i = 0; i < 16; i++) o[i] = 0.0f;
    float m_run = -1e30f, l_run = 0.0f;

    const unsigned char* mrow = mask + ((size_t)b * SEQ + (q0 + r)) * SEQ;

    for (int kv0 = 0; kv0 < SEQ; kv0 += 64) {
        __syncthreads();  // protect smem reuse (also covers Q-load on iter 0)
        const float* Kbase = K + ((size_t)(b * SEQ + kv0)) * DM + h * DK;
        const float* Vbase = V + ((size_t)(b * SEQ + kv0)) * DM + h * DK;
#pragma unroll
        for (int i = 0; i < 4; i++) {
            int s = tid + i * 256;
            int rr = s >> 4;
            int c4 = (s & 15) * 4;
            *(float4*)&Ks[rr * P + c4] = *(const float4*)&Kbase[(size_t)rr * DM + c4];
            *(float4*)&Vs[rr * P + c4] = *(const float4*)&Vbase[(size_t)rr * DM + c4];
        }
        __syncthreads();

        // ---- S = Q K^T (thread owns j = c + 4*jj) ----
        float sv[16];
#pragma unroll
        for (int jj = 0; jj < 16; jj++) sv[jj] = 0.0f;
#pragma unroll
        for (int k4 = 0; k4 < 64; k4 += 4) {
            float4 q4 = *(const float4*)&Qs[r * P + k4];
#pragma unroll
            for (int jj = 0; jj < 16; jj++) {
                float4 kv = *(const float4*)&Ks[(c + 4 * jj) * P + k4];
                sv[jj] = fmaf(q4.x, kv.x, sv[jj]);
                sv[jj] = fmaf(q4.y, kv.y, sv[jj]);
                sv[jj] = fmaf(q4.z, kv.z, sv[jj]);
                sv[jj] = fmaf(q4.w, kv.w, sv[jj]);
            }
        }

        // ---- masked scale + online softmax update ----
        float mloc = -1e30f;
#pragma unroll
        for (int jj = 0; jj < 16; jj++) {
            float x = sv[jj] * scale;
            if (mrow[kv0 + c + 4 * jj]) x = -1e9f;
            sv[jj] = x;
            mloc = fmaxf(mloc, x);
        }
        mloc = fmaxf(mloc, __shfl_xor_sync(0xffffffffu, mloc, 1));
        mloc = fmaxf(mloc, __shfl_xor_sync(0xffffffffu, mloc, 2));
        float m_new = fmaxf(m_run, mloc);
        float corr = __expf(m_run - m_new);
        float lsum = 0.0f;
#pragma unroll
        for (int jj = 0; jj < 16; jj++) {
            float p = __expf(sv[jj] - m_new);
            sv[jj] = p;
            lsum += p;
        }
        lsum += __shfl_xor_sync(0xffffffffu, lsum, 1);
        lsum += __shfl_xor_sync(0xffffffffu, lsum, 2);
        l_run = l_run * corr + lsum;
        m_run = m_new;
#pragma unroll
        for (int i = 0; i < 16; i++) o[i] *= corr;

        // stash P into smem (row r owned by its 4 lanes -> warp-local)
#pragma unroll
        for (int jj = 0; jj < 16; jj++)
            Ps[r * P + c + 4 * jj] = sv[jj];
        __syncwarp();

        // ---- O += P @ V (thread owns d = c*16 + jj) ----
#pragma unroll 8
        for (int j = 0; j < 64; j++) {
            float p = Ps[r * P + j];
#pragma unroll
            for (int jj4 = 0; jj4 < 16; jj4 += 4) {
                float4 vv = *(const float4*)&Vs[j * P + c * 16 + jj4];
                o[jj4 + 0] = fmaf(p, vv.x, o[jj4 + 0]);
                o[jj4 + 1] = fmaf(p, vv.y, o[jj4 + 1]);
                o[jj4 + 2] = fmaf(p, vv.z, o[jj4 + 2]);
                o[jj4 + 3] = fmaf(p, vv.w, o[jj4 + 3]);
            }
        }
        __syncwarp();
    }

    float inv = 1.0f / l_run;
    float* out = CTX + ((size_t)(b * SEQ + q0 + r)) * DM + h * DK + c * 16;
#pragma unroll
    for (int jj4 = 0; jj4 < 16; jj4 += 4) {
        float4 v;
        v.x = o[jj4 + 0] * inv;
        v.y = o[jj4 + 1] * inv;
        v.z = o[jj4 + 2] * inv;
        v.w = o[jj4 + 3] * inv;
        *(float4*)&out[jj4] = v;
    }
}

// ---------------- layernorm over last dim (1024), biased var --------------
__global__ __launch_bounds__(256) void layernorm_kernel(
    const float* __restrict__ X, const float* __restrict__ g,
    const float* __restrict__ bt, float* __restrict__ out)
{
    __shared__ float sh_s[8], sh_ss[8], sh_mean, sh_rstd;
    int row = blockIdx.x;
    int tid = threadIdx.x;
    const float* x = X + (size_t)row * DM;
    float4 xv = *(const float4*)&x[tid * 4];
    float s  = xv.x + xv.y + xv.z + xv.w;
    float ss = xv.x * xv.x + xv.y * xv.y + xv.z * xv.z + xv.w * xv.w;
#pragma unroll
    for (int off = 16; off; off >>= 1) {
        s  += __shfl_xor_sync(0xffffffffu, s, off);
        ss += __shfl_xor_sync(0xffffffffu, ss, off);
    }
    int wid = tid >> 5, lane = tid & 31;
    if (lane == 0) { sh_s[wid] = s; sh_ss[wid] = ss; }
    __syncthreads();
    if (wid == 0) {
        float s2  = (lane < 8) ? sh_s[lane]  : 0.0f;
        float ss2 = (lane < 8) ? sh_ss[lane] : 0.0f;
#pragma unroll
        for (int off = 4; off; off >>= 1) {
            s2  += __shfl_xor_sync(0xffffffffu, s2, off);
            ss2 += __shfl_xor_sync(0xffffffffu, ss2, off);
        }
        if (lane == 0) {
            float mean = s2 * (1.0f / DM);
            float var  = ss2 * (1.0f / DM) - mean * mean;
            sh_mean = mean;
            sh_rstd = rsqrtf(var + 1e-5f);
        }
    }
    __syncthreads();
    float mean = sh_mean, rstd = sh_rstd;
    float4 gv = *(const float4*)&g[tid * 4];
    float4 bv = *(const float4*)&bt[tid * 4];
    float4 ov;
    ov.x = (xv.x - mean) * rstd * gv.x + bv.x;
    ov.y = (xv.y - mean) * rstd * gv.y + bv.y;
    ov.z = (xv.z - mean) * rstd * gv.z + bv.z;
    ov.w = (xv.w - mean) * rstd * gv.w + bv.w;
    *(float4*)&out[(size_t)row * DM + tid * 4] = ov;
}

// -------------------------------- host -----------------------------------
extern "C" void kernel_launch(void* const* d_in, const int* in_sizes, int n_in,
                              void* d_out, int out_size)
{
    const float* X    = (const float*)d_in[0];
    const unsigned char* mask = (const unsigned char*)d_in[1];
    const float* Wq  = (const float*)d_in[2];
    const float* bq  = (const float*)d_in[3];
    const float* Wk  = (const float*)d_in[4];
    const float* bk  = (const float*)d_in[5];
    const float* Wv  = (const float*)d_in[6];
    const float* bv  = (const float*)d_in[7];
    const float* Wo  = (const float*)d_in[8];
    const float* bo  = (const float*)d_in[9];
    const float* g1  = (const float*)d_in[10];
    const float* b1  = (const float*)d_in[11];
    const float* W1  = (const float*)d_in[12];
    const float* bf1 = (const float*)d_in[13];
    const float* W2  = (const float*)d_in[14];
    const float* bf2 = (const float*)d_in[15];
    const float* g2  = (const float*)d_in[16];
    const float* b2  = (const float*)d_in[17];
    float* out = (float*)d_out;

    float *Qp, *Kp, *Vp, *CTXp, *T1p, *AOp, *Hp;
    cudaGetSymbolAddress((void**)&Qp,   g_Q);
    cudaGetSymbolAddress((void**)&Kp,   g_K);
    cudaGetSymbolAddress((void**)&Vp,   g_V);
    cudaGetSymbolAddress((void**)&CTXp, g_CTX);
    cudaGetSymbolAddress((void**)&T1p,  g_T1);
    cudaGetSymbolAddress((void**)&AOp,  g_AO);
    cudaGetSymbolAddress((void**)&Hp,   g_H);

    const int attn_smem = 4 * 64 * 68 * (int)sizeof(float);  // 69632 B
    cudaFuncSetAttribute(attn_kernel,
                         cudaFuncAttributeMaxDynamicSharedMemorySize, attn_smem);

    dim3 gproj(DM / 128, TOKENS / 128);     // (8, 32)
    dim3 gff1(DFF / 128, TOKENS / 128);     // (32, 32)

    // QKV projections
    gemm_kernel<0><<<gproj, 256>>>(X, Wq, bq, nullptr, Qp, TOKENS, DM, DM);
    gemm_kernel<0><<<gproj, 256>>>(X, Wk, bk, nullptr, Kp, TOKENS, DM, DM);
    gemm_kernel<0><<<gproj, 256>>>(X, Wv, bv, nullptr, Vp, TOKENS, DM, DM);

    // attention
    dim3 gattn(SEQ / 64, HEADS, BATCH);     // (32, 16, 2)
    attn_kernel<<<gattn, 256, attn_smem>>>(Qp, Kp, Vp, mask, CTXp);

    // output projection + residual, then LN1
    gemm_kernel<2><<<gproj, 256>>>(CTXp, Wo, bo, X, T1p, TOKENS, DM, DM);
    layernorm_kernel<<<TOKENS, 256>>>(T1p, g1, b1, AOp);

    // FF1 + gelu
    gemm_kernel<1><<<gff1, 256>>>(AOp, W1, bf1, nullptr, Hp, TOKENS, DFF, DM);

    // FF2 + residual, then LN2 -> out
    gemm_kernel<2><<<gproj, 256>>>(Hp, W2, bf2, AOp, T1p, TOKENS, DM, DFF);
    layernorm_kernel<<<TOKENS, 256>>>(T1p, g2, b2, out);
}

// round 4
// speedup vs baseline: 3.0283x; 3.0283x over previous
#include <cuda_runtime.h>
#include <cuda_bf16.h>
#include <math.h>
#include <stdint.h>

#define TOKENS 4096
#define DM     1024
#define DFF    4096
#define HEADS  16
#define DK     64
#define SEQ    2048
#define BATCH  2

__device__ float g_Q[TOKENS * DM];
__device__ float g_K[TOKENS * DM];
__device__ float g_V[TOKENS * DM];
__device__ float g_CTX[TOKENS * DM];
__device__ float g_T1[TOKENS * DM];
__device__ float g_AO[TOKENS * DM];
__device__ float g_H[TOKENS * DFF];
__device__ __nv_bfloat16 g_Ah[TOKENS * DFF];
__device__ __nv_bfloat16 g_Al[TOKENS * DFF];
__device__ __nv_bfloat16 g_Wh[6 * DM * DM + 2 * DM * DFF];
__device__ __nv_bfloat16 g_Wl[6 * DM * DM + 2 * DM * DFF];

__device__ __forceinline__ uint32_t smem_u32(const void* p) {
    uint32_t a;
    asm("{ .reg .u64 t; cvta.to.shared.u64 t, %1; cvt.u32.u64 %0, t; }" : "=r"(a) : "l"(p));
    return a;
}
__device__ __forceinline__ void ldm_x4(uint32_t* r, uint32_t a) {
    asm volatile("ldmatrix.sync.aligned.m8n8.x4.shared.b16 {%0,%1,%2,%3}, [%4];"
        : "=r"(r[0]), "=r"(r[1]), "=r"(r[2]), "=r"(r[3]) : "r"(a));
}
__device__ __forceinline__ void ldm_x2(uint32_t* r, uint32_t a) {
    asm volatile("ldmatrix.sync.aligned.m8n8.x2.shared.b16 {%0,%1}, [%2];"
        : "=r"(r[0]), "=r"(r[1]) : "r"(a));
}
__device__ __forceinline__ void mma16816(float* c, const uint32_t* a, const uint32_t* b) {
    asm volatile("mma.sync.aligned.m16n8k16.row.col.f32.bf16.bf16.f32 "
        "{%0,%1,%2,%3}, {%4,%5,%6,%7}, {%8,%9}, {%0,%1,%2,%3};"
        : "+f"(c[0]), "+f"(c[1]), "+f"(c[2]), "+f"(c[3])
        : "r"(a[0]), "r"(a[1]), "r"(a[2]), "r"(a[3]), "r"(b[0]), "r"(b[1]));
}
__device__ __forceinline__ void cpasync16(uint32_t s, const void* g) {
    asm volatile("cp.async.cg.shared.global [%0], [%1], 16;" :: "r"(s), "l"(g));
}
#define CP_COMMIT() asm volatile("cp.async.commit_group;" ::: "memory")
#define CP_WAIT(n)  asm volatile("cp.async.wait_group %0;" :: "n"(n) : "memory")

__device__ __forceinline__ float gelu_exact(float x) {
    return 0.5f * x * (1.0f + erff(x * 0.70710678118654752f));
}

// fp32 -> bf16 hi/lo (same layout), 4 elems/thread
__global__ __launch_bounds__(256) void split_kernel(
    const float4* __restrict__ X, __nv_bfloat16* __restrict__ H, __nv_bfloat16* __restrict__ L)
{
    int i = blockIdx.x * 256 + threadIdx.x;
    float4 v = X[i];
    __nv_bfloat162 h0 = __floats2bfloat162_rn(v.x, v.y), h1 = __floats2bfloat162_rn(v.z, v.w);
    __nv_bfloat162 l0 = __floats2bfloat162_rn(v.x - __bfloat162float(h0.x), v.y - __bfloat162float(h0.y));
    __nv_bfloat162 l1 = __floats2bfloat162_rn(v.z - __bfloat162float(h1.x), v.w - __bfloat162float(h1.y));
    ((__nv_bfloat162*)H)[2 * i] = h0; ((__nv_bfloat162*)H)[2 * i + 1] = h1;
    ((__nv_bfloat162*)L)[2 * i] = l0; ((__nv_bfloat162*)L)[2 * i + 1] = l1;
}

// W [K,N] fp32 -> Th/Tl [N,K] bf16 (transpose + split)
__global__ void splitT_kernel(const float* __restrict__ W,
    __nv_bfloat16* __restrict__ Th, __nv_bfloat16* __restrict__ Tl, int K, int N)
{
    __shared__ float t[32][33];
    int n0 = blockIdx.x << 5, k0 = blockIdx.y << 5;
    int tx = threadIdx.x, ty = threadIdx.y;
#pragma unroll
    for (int i = 0; i < 4; i++)
        t[ty + 8 * i][tx] = W[(size_t)(k0 + ty + 8 * i) * N + n0 + tx];
    __syncthreads();
#pragma unroll
    for (int i = 0; i < 4; i++) {
        float v = t[tx][ty + 8 * i];
        __nv_bfloat16 hv = __float2bfloat16(v);
        size_t o = (size_t)(n0 + ty + 8 * i) * K + k0 + tx;
        Th[o] = hv;
        Tl[o] = __float2bfloat16(v - __bfloat162float(hv));
    }
}

// ===== mma.sync split-bf16 GEMM: C[M,N]=A@B^T (+epi), B stored [N,K] ======
#define TILE_B 16384
#define BUF_B  65536
#define SM_TOT 131072
template <int EPI>  // 0 bias, 1 bias+gelu, 2 bias+residual
__global__ __launch_bounds__(256) void gemm3_kernel(
    const __nv_bfloat16* __restrict__ Ah, const __nv_bfloat16* __restrict__ Al,
    const __nv_bfloat16* __restrict__ Bh, const __nv_bfloat16* __restrict__ Bl,
    const float* __restrict__ bias, const float* __restrict__ Rres,
    float* __restrict__ C, int N, int K)
{
    extern __shared__ char gsm[];
    uint32_t sb = smem_u32(gsm);
    int tid = threadIdx.x, wid = tid >> 5, lane = tid & 31;
    int rowBase = blockIdx.y * 128, colBase = blockIdx.x * 128;
    int warp_m = (wid & 1) * 64, warp_n = (wid >> 1) * 32;

    float acc[4][4][4];
#pragma unroll
    for (int i = 0; i < 4; i++)
#pragma unroll
        for (int j = 0; j < 4; j++)
#pragma unroll
            for (int e = 0; e < 4; e++) acc[i][j][e] = 0.0f;

    const int NC = K >> 6;

    // ---- issue chunk c's cp.async loads (4 tiles x 128 rows x 128B) ----
    auto issue = [&](int c) {
        int k0 = c << 6, buf = c & 1;
#pragma unroll
        for (int i = 0; i < 16; i++) {
            int t = i >> 2;
            int e = ((i & 3) << 8) + tid;
            int row = e >> 3, seg = e & 7;
            const __nv_bfloat16* src = (t == 0) ? Ah : (t == 1) ? Al : (t == 2) ? Bh : Bl;
            int gr = ((t < 2) ? rowBase : colBase) + row;
            int off = row * 128 + seg * 16;
            off ^= (off >> 3) & 0x70;
            cpasync16(sb + buf * BUF_B + t * TILE_B + off,
                      src + (size_t)gr * K + k0 + seg * 8);
        }
        CP_COMMIT();
    };

    issue(0);
    // per-lane ldmatrix offsets (swizzle applied per access)
    int a_lrow = (lane < 16) ? lane : (lane - 16);
    int a_kadd = (lane < 16) ? 0 : 16;
    int b_lrow = lane & 7;
    int b_kadd = ((lane & 15) >= 8) ? 16 : 0;

    for (int c = 0; c < NC; c++) {
        if (c + 1 < NC) { issue(c + 1); CP_WAIT(1); }
        else CP_WAIT(0);
        __syncthreads();
        uint32_t base = sb + (c & 1) * BUF_B;
#pragma unroll
        for (int ks = 0; ks < 4; ks++) {
            uint32_t aH[4][4], aL[4][4], bH[4][2], bL[4][2];
#pragma unroll
            for (int i = 0; i < 4; i++) {
                int off = (warp_m + 16 * i + a_lrow) * 128 + ks * 32 + a_kadd;
                off ^= (off >> 3) & 0x70;
                ldm_x4(aH[i], base + off);
                ldm_x4(aL[i], base + TILE_B + off);
            }
#pragma unroll
            for (int j = 0; j < 4; j++) {
                int off = (warp_n + 8 * j + b_lrow) * 128 + ks * 32 + b_kadd;
                off ^= (off >> 3) & 0x70;
                ldm_x2(bH[j], base + 2 * TILE_B + off);
                ldm_x2(bL[j], base + 3 * TILE_B + off);
            }
#pragma unroll
            for (int i = 0; i < 4; i++)
#pragma unroll
                for (int j = 0; j < 4; j++) {
                    mma16816(acc[i][j], aH[i], bH[j]);
                    mma16816(acc[i][j], aH[i], bL[j]);
                    mma16816(acc[i][j], aL[i], bH[j]);
                }
        }
        __syncthreads();
    }

    // ---- epilogue ----
    int quad = lane >> 2, pos = lane & 3;
#pragma unroll
    for (int i = 0; i < 4; i++)
#pragma unroll
        for (int j = 0; j < 4; j++) {
            int col = colBase + warp_n + 8 * j + 2 * pos;
            float2 bz = *(const float2*)&bias[col];
#pragma unroll
            for (int h = 0; h < 2; h++) {
                size_t row = rowBase + warp_m + 16 * i + quad + 8 * h;
                float vx = acc[i][j][2 * h] + bz.x;
                float vy = acc[i][j][2 * h + 1] + bz.y;
                if (EPI == 2) {
                    float2 rv = *(const float2*)&Rres[row * N + col];
                    vx += rv.x; vy += rv.y;
                }
                if (EPI == 1) { vx = gelu_exact(vx); vy = gelu_exact(vy); }
                *(float2*)&C[row * N + col] = make_float2(vx, vy);
            }
        }
}

// ======== flash attention fp32, 4x4 register tiling + smem mask ==========
// block 256 = (tx 0-15, ty 0-15); thread: rows 4ty..4ty+3, cols tx+16j
#define ATT_P   68
#define ATT_MS  (4 * 64 * ATT_P * 4)          // float area
#define ATT_SM  (ATT_MS + 64 * 64)            // + mask bytes
__global__ __launch_bounds__(256, 2) void attn_kernel(
    const float* __restrict__ Q, const float* __restrict__ K,
    const float* __restrict__ V, const unsigned char* __restrict__ mask,
    float* __restrict__ CTX)
{
    const int P = ATT_P;
    extern __shared__ float sm[];
    float* Qs = sm;
    float* Ks = sm + 64 * P;
    float* Vs = sm + 2 * 64 * P;
    float* Ps = sm + 3 * 64 * P;
    unsigned char* Ms = (unsigned char*)(sm + 4 * 64 * P);

    int tid = threadIdx.x;
    int tx = tid & 15, ty = tid >> 4;
    int q0 = blockIdx.x * 64, h = blockIdx.y, b = blockIdx.z;
    const float scale = 0.125f;

    const float* Qbase = Q + ((size_t)(b * SEQ + q0)) * DM + h * DK;
#pragma unroll
    for (int i = 0; i < 4; i++) {
        int s = tid + i * 256, rr = s >> 4, c4 = (s & 15) * 4;
        *(float4*)&Qs[rr * P + c4] = *(const float4*)&Qbase[(size_t)rr * DM + c4];
    }

    float o[4][4], m_run[4], l_run[4];
#pragma unroll
    for (int i = 0; i < 4; i++) {
        m_run[i] = -1e30f; l_run[i] = 0.0f;
#pragma unroll
        for (int j = 0; j < 4; j++) o[i][j] = 0.0f;
    }
    int mrow_base = tid >> 2, mseg = tid & 3;
    const unsigned char* mblk = mask + ((size_t)(b * SEQ + q0 + mrow_base)) * SEQ;

    for (int kv0 = 0; kv0 < SEQ; kv0 += 64) {
        __syncthreads();
        const float* Kb = K + ((size_t)(b * SEQ + kv0)) * DM + h * DK;
        const float* Vb = V + ((size_t)(b * SEQ + kv0)) * DM + h * DK;
#pragma unroll
        for (int i = 0; i < 4; i++) {
            int s = tid + i * 256, rr = s >> 4, c4 = (s & 15) * 4;
            *(float4*)&Ks[rr * P + c4] = *(const float4*)&Kb[(size_t)rr * DM + c4];
            *(float4*)&Vs[rr * P + c4] = *(const float4*)&Vb[(size_t)rr * DM + c4];
        }
        // mask tile: 64 rows x 64 bytes, 1 uint4 per thread
        *(uint4*)&Ms[mrow_base * 64 + mseg * 16] =
            *(const uint4*)&mblk[kv0 + mseg * 16];
        __syncthreads();

        // ---- S = Q K^T (4x4 per thread) ----
        float sv[4][4];
#pragma unroll
        for (int i = 0; i < 4; i++)
#pragma unroll
            for (int j = 0; j < 4; j++) sv[i][j] = 0.0f;
#pragma unroll
        for (int k4 = 0; k4 < 64; k4 += 4) {
            float4 qa[4], kb[4];
#pragma unroll
            for (int i = 0; i < 4; i++) qa[i] = *(float4*)&Qs[(ty * 4 + i) * P + k4];
#pragma unroll
            for (int j = 0; j < 4; j++) kb[j] = *(float4*)&Ks[(tx + 16 * j) * P + k4];
#pragma unroll
            for (int i = 0; i < 4; i++)
#pragma unroll
                for (int j = 0; j < 4; j++) {
                    sv[i][j] = fmaf(qa[i].x, kb[j].x, sv[i][j]);
                    sv[i][j] = fmaf(qa[i].y, kb[j].y, sv[i][j]);
                    sv[i][j] = fmaf(qa[i].z, kb[j].z, sv[i][j]);
                    sv[i][j] = fmaf(qa[i].w, kb[j].w, sv[i][j]);
                }
        }

        // ---- mask + scale + online softmax (reduce over tx halves) ----
#pragma unroll
        for (int i = 0; i < 4; i++) {
            float mm = -1e30f;
#pragma unroll
            for (int j = 0; j < 4; j++) {
                float x = sv[i][j] * scale;
                if (Ms[(ty * 4 + i) * 64 + tx + 16 * j]) x = -1e9f;
                sv[i][j] = x;
                mm = fmaxf(mm, x);
            }
            mm = fmaxf(mm, __shfl_xor_sync(0xffffffffu, mm, 1));
            mm = fmaxf(mm, __shfl_xor_sync(0xffffffffu, mm, 2));
            mm = fmaxf(mm, __shfl_xor_sync(0xffffffffu, mm, 4));
            mm = fmaxf(mm, __shfl_xor_sync(0xffffffffu, mm, 8));
            float m_new = fmaxf(m_run[i], mm);
            float corr = __expf(m_run[i] - m_new);
            float ls = 0.0f;
#pragma unroll
            for (int j = 0; j < 4; j++) {
                float p = __expf(sv[i][j] - m_new);
                sv[i][j] = p;
                ls += p;
            }
            ls += __shfl_xor_sync(0xffffffffu, ls, 1);
            ls += __shfl_xor_sync(0xffffffffu, ls, 2);
            ls += __shfl_xor_sync(0xffffffffu, ls, 4);
            ls += __shfl_xor_sync(0xffffffffu, ls, 8);
            l_run[i] = l_run[i] * corr + ls;
            m_run[i] = m_new;
#pragma unroll
            for (int j = 0; j < 4; j++) {
                o[i][j] *= corr;
                Ps[(ty * 4 + i) * P + tx + 16 * j] = sv[i][j];
            }
        }
        __syncthreads();

        // ---- O += P @ V ----
#pragma unroll 4
        for (int k4 = 0; k4 < 64; k4 += 4) {
            float4 pa[4];
#pragma unroll
            for (int i = 0; i < 4; i++) pa[i] = *(float4*)&Ps[(ty * 4 + i) * P + k4];
#pragma unroll
            for (int q = 0; q < 4; q++) {
                float pv[4];
#pragma unroll
                for (int j = 0; j < 4; j++) pv[j] = Vs[(k4 + q) * P + tx + 16 * j];
#pragma unroll
                for (int i = 0; i < 4; i++) {
                    float pq = (q == 0) ? pa[i].x : (q == 1) ? pa[i].y
                             : (q == 2) ? pa[i].z : pa[i].w;
#pragma unroll
                    for (int j = 0; j < 4; j++)
                        o[i][j] = fmaf(pq, pv[j], o[i][j]);
                }
            }
        }
    }

    float* outp = CTX + ((size_t)(b * SEQ + q0)) * DM + h * DK;
#pragma unroll
    for (int i = 0; i < 4; i++) {
        float inv = 1.0f / l_run[i];
#pragma unroll
        for (int j = 0; j < 4; j++)
            outp[(size_t)(ty * 4 + i) * DM + tx + 16 * j] = o[i][j] * inv;
    }
}

// ---------------- layernorm (biased var) ----------------------------------
__global__ __launch_bounds__(256) void layernorm_kernel(
    const float* __restrict__ X, const float* __restrict__ g,
    const float* __restrict__ bt, float* __restrict__ out)
{
    __shared__ float sh_s[8], sh_ss[8], sh_m, sh_r;
    int row = blockIdx.x, tid = threadIdx.x;
    const float* x = X + (size_t)row * DM;
    float4 xv = *(const float4*)&x[tid * 4];
    float s = xv.x + xv.y + xv.z + xv.w;
    float ss = xv.x * xv.x + xv.y * xv.y + xv.z * xv.z + xv.w * xv.w;
#pragma unroll
    for (int off = 16; off; off >>= 1) {
        s += __shfl_xor_sync(0xffffffffu, s, off);
        ss += __shfl_xor_sync(0xffffffffu, ss, off);
    }
    int wid = tid >> 5, lane = tid & 31;
    if (lane == 0) { sh_s[wid] = s; sh_ss[wid] = ss; }
    __syncthreads();
    if (wid == 0) {
        float s2 = (lane < 8) ? sh_s[lane] : 0.0f;
        float ss2 = (lane < 8) ? sh_ss[lane] : 0.0f;
#pragma unroll
        for (int off = 4; off; off >>= 1) {
            s2 += __shfl_xor_sync(0xffffffffu, s2, off);
            ss2 += __shfl_xor_sync(0xffffffffu, ss2, off);
        }
        if (lane == 0) {
            float mean = s2 * (1.0f / DM);
            sh_m = mean;
            sh_r = rsqrtf(ss2 * (1.0f / DM) - mean * mean + 1e-5f);
        }
    }
    __syncthreads();
    float mean = sh_m, rstd = sh_r;
    float4 gv = *(const float4*)&g[tid * 4];
    float4 bv = *(const float4*)&bt[tid * 4];
    float4 ov;
    ov.x = (xv.x - mean) * rstd * gv.x + bv.x;
    ov.y = (xv.y - mean) * rstd * gv.y + bv.y;
    ov.z = (xv.z - mean) * rstd * gv.z + bv.z;
    ov.w = (xv.w - mean) * rstd * gv.w + bv.w;
    *(float4*)&out[(size_t)row * DM + tid * 4] = ov;
}

// -------------------------------- host -----------------------------------
extern "C" void kernel_launch(void* const* d_in, const int* in_sizes, int n_in,
                              void* d_out, int out_size)
{
    const float* X = (const float*)d_in[0];
    const unsigned char* mask = (const unsigned char*)d_in[1];
    const float *Wq = (const float*)d_in[2], *bq = (const float*)d_in[3];
    const float *Wk = (const float*)d_in[4], *bk = (const float*)d_in[5];
    const float *Wv = (const float*)d_in[6], *bv = (const float*)d_in[7];
    const float *Wo = (const float*)d_in[8], *bo = (const float*)d_in[9];
    const float *g1 = (const float*)d_in[10], *b1 = (const float*)d_in[11];
    const float *W1 = (const float*)d_in[12], *bf1 = (const float*)d_in[13];
    const float *W2 = (const float*)d_in[14], *bf2 = (const float*)d_in[15];
    const float *g2 = (const float*)d_in[16], *b2 = (const float*)d_in[17];
    float* out = (float*)d_out;

    float *Qp, *Kp, *Vp, *CTXp, *T1p, *AOp, *Hp;
    cudaGetSymbolAddress((void**)&Qp, g_Q);
    cudaGetSymbolAddress((void**)&Kp, g_K);
    cudaGetSymbolAddress((void**)&Vp, g_V);
    cudaGetSymbolAddress((void**)&CTXp, g_CTX);
    cudaGetSymbolAddress((void**)&T1p, g_T1);
    cudaGetSymbolAddress((void**)&AOp, g_AO);
    cudaGetSymbolAddress((void**)&Hp, g_H);
    __nv_bfloat16 *Ah, *Al, *Wh, *Wl;
    cudaGetSymbolAddress((void**)&Ah, g_Ah);
    cudaGetSymbolAddress((void**)&Al, g_Al);
    cudaGetSymbolAddress((void**)&Wh, g_Wh);
    cudaGetSymbolAddress((void**)&Wl, g_Wl);
    const size_t S1 = (size_t)DM * DM;
    __nv_bfloat16 *qh = Wh, *kh = Wh + S1, *vh = Wh + 2 * S1, *oh = Wh + 3 * S1;
    __nv_bfloat16 *w1h = Wh + 4 * S1, *w2h = Wh + 4 * S1 + (size_t)DM * DFF;
    __nv_bfloat16 *ql = Wl, *kl = Wl + S1, *vl = Wl + 2 * S1, *ol = Wl + 3 * S1;
    __nv_bfloat16 *w1l = Wl + 4 * S1, *w2l = Wl + 4 * S1 + (size_t)DM * DFF;

    cudaFuncSetAttribute(gemm3_kernel<0>, cudaFuncAttributeMaxDynamicSharedMemorySize, SM_TOT);
    cudaFuncSetAttribute(gemm3_kernel<1>, cudaFuncAttributeMaxDynamicSharedMemorySize, SM_TOT);
    cudaFuncSetAttribute(gemm3_kernel<2>, cudaFuncAttributeMaxDynamicSharedMemorySize, SM_TOT);
    cudaFuncSetAttribute(attn_kernel, cudaFuncAttributeMaxDynamicSharedMemorySize, ATT_SM);

    dim3 tb(32, 8);
    splitT_kernel<<<dim3(DM / 32, DM / 32), tb>>>(Wq, qh, ql, DM, DM);
    splitT_kernel<<<dim3(DM / 32, DM / 32), tb>>>(Wk, kh, kl, DM, DM);
    splitT_kernel<<<dim3(DM / 32, DM / 32), tb>>>(Wv, vh, vl, DM, DM);
    splitT_kernel<<<dim3(DM / 32, DM / 32), tb>>>(Wo, oh, ol, DM, DM);
    splitT_kernel<<<dim3(DFF / 32, DM / 32), tb>>>(W1, w1h, w1l, DM, DFF);
    splitT_kernel<<<dim3(DM / 32, DFF / 32), tb>>>(W2, w2h, w2l, DFF, DM);

    dim3 gproj(DM / 128, TOKENS / 128), gff1(DFF / 128, TOKENS / 128);

    split_kernel<<<(TOKENS * DM) / 1024, 256>>>((const float4*)X, Ah, Al);
    gemm3_kernel<0><<<gproj, 256, SM_TOT>>>(Ah, Al, qh, ql, bq, nullptr, Qp, DM, DM);
    gemm3_kernel<0><<<gproj, 256, SM_TOT>>>(Ah, Al, kh, kl, bk, nullptr, Kp, DM, DM);
    gemm3_kernel<0><<<gproj, 256, SM_TOT>>>(Ah, Al, vh, vl, bv, nullptr, Vp, DM, DM);

    dim3 gattn(SEQ / 64, HEADS, BATCH);
    attn_kernel<<<gattn, 256, ATT_SM>>>(Qp, Kp, Vp, mask, CTXp);

    split_kernel<<<(TOKENS * DM) / 1024, 256>>>((const float4*)CTXp, Ah, Al);
    gemm3_kernel<2><<<gproj, 256, SM_TOT>>>(Ah, Al, oh, ol, bo, X, T1p, DM, DM);
    layernorm_kernel<<<TOKENS, 256>>>(T1p, g1, b1, AOp);

    split_kernel<<<(TOKENS * DM) / 1024, 256>>>((const float4*)AOp, Ah, Al);
    gemm3_kernel<1><<<gff1, 256, SM_TOT>>>(Ah, Al, w1h, w1l, bf1, nullptr, Hp, DFF, DM);

    split_kernel<<<(TOKENS * DFF) / 1024, 256>>>((const float4*)Hp, Ah, Al);
    gemm3_kernel<2><<<gproj, 256, SM_TOT>>>(Ah, Al, w2h, w2l, bf2, AOp, T1p, DM, DFF);
    layernorm_kernel<<<TOKENS, 256>>>(T1p, g2, b2, out);
}

// round 5
// speedup vs baseline: 4.6335x; 1.5301x over previous
#include <cuda_runtime.h>
#include <cuda_bf16.h>
#include <math.h>
#include <stdint.h>

#define TOKENS 4096
#define DM     1024
#define DFF    4096
#define HEADS  16
#define DK     64
#define SEQ    2048
#define BATCH  2

// ---------------- scratch (device globals) --------------------------------
__device__ float g_T1[TOKENS * DM];
__device__ float g_AO[TOKENS * DM];
__device__ __nv_bfloat16 g_Xh[TOKENS * DM],  g_Xl[TOKENS * DM];
__device__ __nv_bfloat16 g_Qh[TOKENS * DM],  g_Ql[TOKENS * DM];
__device__ __nv_bfloat16 g_Kh[TOKENS * DM],  g_Kl[TOKENS * DM];
__device__ __nv_bfloat16 g_Vh[TOKENS * DM],  g_Vl[TOKENS * DM];
__device__ __nv_bfloat16 g_Ch[TOKENS * DM],  g_Cl[TOKENS * DM];
__device__ __nv_bfloat16 g_AOh[TOKENS * DM], g_AOl[TOKENS * DM];
__device__ __nv_bfloat16 g_Hh[TOKENS * DFF], g_Hl[TOKENS * DFF];
__device__ __nv_bfloat16 g_Wh[4 * DM * DM + 2 * DM * DFF];
__device__ __nv_bfloat16 g_Wl[4 * DM * DM + 2 * DM * DFF];
__device__ unsigned char g_MB[BATCH * SEQ * SEQ / 8];

// ---------------- ptx helpers ---------------------------------------------
__device__ __forceinline__ uint32_t smem_u32(const void* p) {
    uint32_t a;
    asm("{ .reg .u64 t; cvta.to.shared.u64 t, %1; cvt.u32.u64 %0, t; }" : "=r"(a) : "l"(p));
    return a;
}
__device__ __forceinline__ void ldm_x4(uint32_t* r, uint32_t a) {
    asm volatile("ldmatrix.sync.aligned.m8n8.x4.shared.b16 {%0,%1,%2,%3}, [%4];"
        : "=r"(r[0]), "=r"(r[1]), "=r"(r[2]), "=r"(r[3]) : "r"(a));
}
__device__ __forceinline__ void ldm_x2(uint32_t* r, uint32_t a) {
    asm volatile("ldmatrix.sync.aligned.m8n8.x2.shared.b16 {%0,%1}, [%2];"
        : "=r"(r[0]), "=r"(r[1]) : "r"(a));
}
__device__ __forceinline__ void ldm_x2t(uint32_t* r, uint32_t a) {
    asm volatile("ldmatrix.sync.aligned.m8n8.x2.trans.shared.b16 {%0,%1}, [%2];"
        : "=r"(r[0]), "=r"(r[1]) : "r"(a));
}
__device__ __forceinline__ void mma16816(float* c, const uint32_t* a, const uint32_t* b) {
    asm volatile("mma.sync.aligned.m16n8k16.row.col.f32.bf16.bf16.f32 "
        "{%0,%1,%2,%3}, {%4,%5,%6,%7}, {%8,%9}, {%0,%1,%2,%3};"
        : "+f"(c[0]), "+f"(c[1]), "+f"(c[2]), "+f"(c[3])
        : "r"(a[0]), "r"(a[1]), "r"(a[2]), "r"(a[3]), "r"(b[0]), "r"(b[1]));
}
__device__ __forceinline__ void cpasync16(uint32_t s, const void* g) {
    asm volatile("cp.async.cg.shared.global [%0], [%1], 16;" :: "r"(s), "l"(g));
}
__device__ __forceinline__ void cpasync8(uint32_t s, const void* g) {
    asm volatile("cp.async.ca.shared.global [%0], [%1], 8;" :: "r"(s), "l"(g));
}
#define CP_COMMIT() asm volatile("cp.async.commit_group;" ::: "memory")
#define CP_WAIT(n)  asm volatile("cp.async.wait_group %0;" :: "n"(n) : "memory")

__device__ __forceinline__ float gelu_exact(float x) {
    return 0.5f * x * (1.0f + erff(x * 0.70710678118654752f));
}
__device__ __forceinline__ void pack_hl(float x, float y, uint32_t& h, uint32_t& l) {
    __nv_bfloat162 hh = __floats2bfloat162_rn(x, y);
    __nv_bfloat162 ll = __floats2bfloat162_rn(x - __bfloat162float(hh.x),
                                              y - __bfloat162float(hh.y));
    h = reinterpret_cast<uint32_t&>(hh);
    l = reinterpret_cast<uint32_t&>(ll);
}

// ---------------- small prep kernels --------------------------------------
__global__ __launch_bounds__(256) void split_kernel(
    const float4* __restrict__ X, __nv_bfloat16* __restrict__ H, __nv_bfloat16* __restrict__ L)
{
    int i = blockIdx.x * 256 + threadIdx.x;
    float4 v = X[i];
    uint32_t h0, l0, h1, l1;
    pack_hl(v.x, v.y, h0, l0);
    pack_hl(v.z, v.w, h1, l1);
    ((uint32_t*)H)[2 * i] = h0; ((uint32_t*)H)[2 * i + 1] = h1;
    ((uint32_t*)L)[2 * i] = l0; ((uint32_t*)L)[2 * i + 1] = l1;
}

__global__ __launch_bounds__(256) void maskbits_kernel(
    const unsigned char* __restrict__ m, unsigned char* __restrict__ bits)
{
    int i = blockIdx.x * 256 + threadIdx.x;
    unsigned long long v = *(const unsigned long long*)(m + 8ull * i);
    unsigned r = 0;
#pragma unroll
    for (int j = 0; j < 8; j++)
        r |= (((v >> (8 * j)) & 0xffull) ? 1u : 0u) << j;
    bits[i] = (unsigned char)r;
}

// W [K,N] fp32 -> Th/Tl [N,K] bf16 (transpose + split)
__global__ void splitT_kernel(const float* __restrict__ W,
    __nv_bfloat16* __restrict__ Th, __nv_bfloat16* __restrict__ Tl, int K, int N)
{
    __shared__ float t[32][33];
    int n0 = blockIdx.x << 5, k0 = blockIdx.y << 5;
    int tx = threadIdx.x, ty = threadIdx.y;
#pragma unroll
    for (int i = 0; i < 4; i++)
        t[ty + 8 * i][tx] = W[(size_t)(k0 + ty + 8 * i) * N + n0 + tx];
    __syncthreads();
#pragma unroll
    for (int i = 0; i < 4; i++) {
        float v = t[tx][ty + 8 * i];
        __nv_bfloat16 hv = __float2bfloat16(v);
        size_t o = (size_t)(n0 + ty + 8 * i) * K + k0 + tx;
        Th[o] = hv;
        Tl[o] = __float2bfloat16(v - __bfloat162float(hv));
    }
}

// ===== mma.sync split-bf16 GEMM: C[M,N] = A@B^T (+epi), B stored [N,K] ====
#define TILE_B 16384
#define BUF_B  65536
#define SM_TOT 131072
// EPI: 0 bias, 1 bias+gelu, 2 bias+residual.  OM: 0 fp32 C, 1 bf16 hi/lo pair
template <int EPI, int OM>
__global__ __launch_bounds__(256) void gemm3_kernel(
    const __nv_bfloat16* __restrict__ Ah, const __nv_bfloat16* __restrict__ Al,
    const __nv_bfloat16* __restrict__ Bh, const __nv_bfloat16* __restrict__ Bl,
    const float* __restrict__ bias, const float* __restrict__ Rres,
    float* __restrict__ C, __nv_bfloat16* __restrict__ Ch, __nv_bfloat16* __restrict__ Cl,
    int N, int K)
{
    extern __shared__ char gsm[];
    uint32_t sb = smem_u32(gsm);
    int tid = threadIdx.x, wid = tid >> 5, lane = tid & 31;
    int rowBase = blockIdx.y * 128, colBase = blockIdx.x * 128;
    int warp_m = (wid & 1) * 64, warp_n = (wid >> 1) * 32;

    float acc[4][4][4];
#pragma unroll
    for (int i = 0; i < 4; i++)
#pragma unroll
        for (int j = 0; j < 4; j++)
#pragma unroll
            for (int e = 0; e < 4; e++) acc[i][j][e] = 0.0f;

    const int NC = K >> 6;
    auto issue = [&](int c) {
        int k0 = c << 6, buf = c & 1;
#pragma unroll
        for (int i = 0; i < 16; i++) {
            int t = i >> 2;
            int e = ((i & 3) << 8) + tid;
            int row = e >> 3, seg = e & 7;
            const __nv_bfloat16* src = (t == 0) ? Ah : (t == 1) ? Al : (t == 2) ? Bh : Bl;
            int gr = ((t < 2) ? rowBase : colBase) + row;
            int off = row * 128 + seg * 16;
            off ^= (off >> 3) & 0x70;
            cpasync16(sb + buf * BUF_B + t * TILE_B + off,
                      src + (size_t)gr * K + k0 + seg * 8);
        }
        CP_COMMIT();
    };

    issue(0);
    int a_lrow = lane & 15, a_kadd = (lane < 16) ? 0 : 16;
    int b_lrow = lane & 7, b_kadd = ((lane & 15) >= 8) ? 16 : 0;

    for (int c = 0; c < NC; c++) {
        if (c + 1 < NC) { issue(c + 1); CP_WAIT(1); }
        else CP_WAIT(0);
        __syncthreads();
        uint32_t base = sb + (c & 1) * BUF_B;
#pragma unroll
        for (int ks = 0; ks < 4; ks++) {
            uint32_t aH[4][4], aL[4][4], bH[4][2], bL[4][2];
#pragma unroll
            for (int i = 0; i < 4; i++) {
                int off = (warp_m + 16 * i + a_lrow) * 128 + ks * 32 + a_kadd;
                off ^= (off >> 3) & 0x70;
                ldm_x4(aH[i], base + off);
                ldm_x4(aL[i], base + TILE_B + off);
            }
#pragma unroll
            for (int j = 0; j < 4; j++) {
                int off = (warp_n + 8 * j + b_lrow) * 128 + ks * 32 + b_kadd;
                off ^= (off >> 3) & 0x70;
                ldm_x2(bH[j], base + 2 * TILE_B + off);
                ldm_x2(bL[j], base + 3 * TILE_B + off);
            }
#pragma unroll
            for (int i = 0; i < 4; i++)
#pragma unroll
                for (int j = 0; j < 4; j++) {
                    mma16816(acc[i][j], aH[i], bH[j]);
                    mma16816(acc[i][j], aH[i], bL[j]);
                    mma16816(acc[i][j], aL[i], bH[j]);
                }
        }
        __syncthreads();
    }

    int quad = lane >> 2, pos = lane & 3;
#pragma unroll
    for (int i = 0; i < 4; i++)
#pragma unroll
        for (int j = 0; j < 4; j++) {
            int col = colBase + warp_n + 8 * j + 2 * pos;
            float2 bz = *(const float2*)&bias[col];
#pragma unroll
            for (int h = 0; h < 2; h++) {
                size_t row = rowBase + warp_m + 16 * i + quad + 8 * h;
                float vx = acc[i][j][2 * h] + bz.x;
                float vy = acc[i][j][2 * h + 1] + bz.y;
                if (EPI == 2) {
                    float2 rv = *(const float2*)&Rres[row * N + col];
                    vx += rv.x; vy += rv.y;
                }
                if (EPI == 1) { vx = gelu_exact(vx); vy = gelu_exact(vy); }
                if (OM == 0) {
                    *(float2*)&C[row * N + col] = make_float2(vx, vy);
                } else {
                    uint32_t hw, lw;
                    pack_hl(vx, vy, hw, lw);
                    ((uint32_t*)Ch)[(row * N + col) >> 1] = hw;
                    ((uint32_t*)Cl)[(row * N + col) >> 1] = lw;
                }
            }
        }
}

// ======== tensor-core flash attention (split bf16, online softmax) ========
// CTA: 256 thr (8 warps), 128 q-rows, kv tile 64, double-buffered K/V/mask
#define AQ    32768
#define ABUF  33792
#define ASM   (AQ + 2 * ABUF)   // 100352 bytes
__global__ void __launch_bounds__(256, 2) attn_kernel(
    const __nv_bfloat16* __restrict__ Qh_, const __nv_bfloat16* __restrict__ Ql_,
    const __nv_bfloat16* __restrict__ Kh_, const __nv_bfloat16* __restrict__ Kl_,
    const __nv_bfloat16* __restrict__ Vh_, const __nv_bfloat16* __restrict__ Vl_,
    const unsigned char* __restrict__ MB,
    __nv_bfloat16* __restrict__ Ch_, __nv_bfloat16* __restrict__ Cl_)
{
    extern __shared__ char sm[];
    uint32_t sb = smem_u32(sm);
    int tid = threadIdx.x, w = tid >> 5, lane = tid & 31;
    int quad = lane >> 2, pos = lane & 3;
    int q0 = blockIdx.x * 128, h = blockIdx.y, b = blockIdx.z;
    size_t qrow0 = (size_t)b * SEQ + q0;
    const float scale = 0.125f;

    // Q tile loads (grouped with kv tile 0)
#pragma unroll
    for (int i = 0; i < 8; i++) {
        int e = tid + i * 256;
        const __nv_bfloat16* src = (e < 1024) ? Qh_ : Ql_;
        int idx = e & 1023, row = idx >> 3, seg = idx & 7;
        int off = row * 128 + seg * 16;
        off ^= (off >> 3) & 0x70;
        cpasync16(sb + ((e < 1024) ? 0 : 16384) + off,
                  src + (qrow0 + row) * DM + h * 64 + seg * 8);
    }
    auto issue_kv = [&](int c) {
        int kv0 = c * 64;
        uint32_t base = sb + AQ + (c & 1) * ABUF;
        size_t krow0 = (size_t)b * SEQ + kv0;
#pragma unroll
        for (int i = 0; i < 8; i++) {
            int e = tid + i * 256;
            int t = e >> 9, idx = e & 511, row = idx >> 3, seg = idx & 7;
            const __nv_bfloat16* src = (t == 0) ? Kh_ : (t == 1) ? Kl_ : (t == 2) ? Vh_ : Vl_;
            int off = row * 128 + seg * 16;
            off ^= (off >> 3) & 0x70;
            cpasync16(base + t * 8192 + off, src + (krow0 + row) * DM + h * 64 + seg * 8);
        }
        if (tid < 128)
            cpasync8(base + 32768 + tid * 8,
                     MB + (qrow0 + tid) * (SEQ / 8) + (kv0 >> 3));
    };
    issue_kv(0); CP_COMMIT();
    issue_kv(1); CP_COMMIT();

    float s[8][4], o[8][4];
    float m0 = -1e30f, m1 = -1e30f, l0 = 0.0f, l1 = 0.0f;
#pragma unroll
    for (int nt = 0; nt < 8; nt++)
#pragma unroll
        for (int e = 0; e < 4; e++) o[nt][e] = 0.0f;

    int a_lrow = lane & 15, a_kadd = (lane < 16) ? 0 : 16;
    int b_lrow = lane & 7, b_kadd = ((lane & 15) >= 8) ? 16 : 0;
    const int NT = SEQ / 64;

    for (int c = 0; c < NT; c++) {
        if (c + 1 < NT) { issue_kv(c + 1); CP_COMMIT(); CP_WAIT(1); }
        else CP_WAIT(0);
        __syncthreads();
        uint32_t base = sb + AQ + (c & 1) * ABUF;
        const char* bufp = sm + AQ + (c & 1) * ABUF;

#pragma unroll
        for (int nt = 0; nt < 8; nt++)
#pragma unroll
            for (int e = 0; e < 4; e++) s[nt][e] = 0.0f;

        // ---- S = Q K^T (3 split passes) ----
#pragma unroll
        for (int ks = 0; ks < 4; ks++) {
            uint32_t qh[4], ql[4];
            int aoff = (w * 16 + a_lrow) * 128 + ks * 32 + a_kadd;
            aoff ^= (aoff >> 3) & 0x70;
            ldm_x4(qh, sb + aoff);
            ldm_x4(ql, sb + 16384 + aoff);
#pragma unroll
            for (int nt = 0; nt < 8; nt++) {
                int boff = (nt * 8 + b_lrow) * 128 + ks * 32 + b_kadd;
                boff ^= (boff >> 3) & 0x70;
                uint32_t kh[2], kl[2];
                ldm_x2(kh, base + boff);
                ldm_x2(kl, base + 8192 + boff);
                mma16816(s[nt], qh, kh);
                mma16816(s[nt], qh, kl);
                mma16816(s[nt], ql, kh);
            }
        }

        // ---- scale + mask + online softmax ----
        unsigned long long bits0 = *(const unsigned long long*)(bufp + 32768 + (w * 16 + quad) * 8);
        unsigned long long bits1 = *(const unsigned long long*)(bufp + 32768 + (w * 16 + quad + 8) * 8);
#pragma unroll
        for (int nt = 0; nt < 8; nt++)
#pragma unroll
            for (int e = 0; e < 4; e++) s[nt][e] *= scale;
        if (bits0) {
#pragma unroll
            for (int nt = 0; nt < 8; nt++) {
                if ((bits0 >> (nt * 8 + 2 * pos)) & 1)     s[nt][0] = -1e9f;
                if ((bits0 >> (nt * 8 + 2 * pos + 1)) & 1) s[nt][1] = -1e9f;
            }
        }
        if (bits1) {
#pragma unroll
            for (int nt = 0; nt < 8; nt++) {
                if ((bits1 >> (nt * 8 + 2 * pos)) & 1)     s[nt][2] = -1e9f;
                if ((bits1 >> (nt * 8 + 2 * pos + 1)) & 1) s[nt][3] = -1e9f;
            }
        }
        float mm0 = -1e30f, mm1 = -1e30f;
#pragma unroll
        for (int nt = 0; nt < 8; nt++) {
            mm0 = fmaxf(mm0, fmaxf(s[nt][0], s[nt][1]));
            mm1 = fmaxf(mm1, fmaxf(s[nt][2], s[nt][3]));
        }
        mm0 = fmaxf(mm0, __shfl_xor_sync(0xffffffffu, mm0, 1));
        mm0 = fmaxf(mm0, __shfl_xor_sync(0xffffffffu, mm0, 2));
        mm1 = fmaxf(mm1, __shfl_xor_sync(0xffffffffu, mm1, 1));
        mm1 = fmaxf(mm1, __shfl_xor_sync(0xffffffffu, mm1, 2));
        float mn0 = fmaxf(m0, mm0), mn1 = fmaxf(m1, mm1);
        float c0 = __expf(m0 - mn0), c1 = __expf(m1 - mn1);
        float ls0 = 0.0f, ls1 = 0.0f;
#pragma unroll
        for (int nt = 0; nt < 8; nt++) {
            s[nt][0] = __expf(s[nt][0] - mn0);
            s[nt][1] = __expf(s[nt][1] - mn0);
            s[nt][2] = __expf(s[nt][2] - mn1);
            s[nt][3] = __expf(s[nt][3] - mn1);
            ls0 += s[nt][0] + s[nt][1];
            ls1 += s[nt][2] + s[nt][3];
        }
        ls0 += __shfl_xor_sync(0xffffffffu, ls0, 1);
        ls0 += __shfl_xor_sync(0xffffffffu, ls0, 2);
        ls1 += __shfl_xor_sync(0xffffffffu, ls1, 1);
        ls1 += __shfl_xor_sync(0xffffffffu, ls1, 2);
        l0 = l0 * c0 + ls0; l1 = l1 * c1 + ls1;
        m0 = mn0; m1 = mn1;
#pragma unroll
        for (int nt = 0; nt < 8; nt++) {
            o[nt][0] *= c0; o[nt][1] *= c0;
            o[nt][2] *= c1; o[nt][3] *= c1;
        }

        // ---- O += P V (3 split passes), P frags built from S acc ----
#pragma unroll
        for (int ks = 0; ks < 4; ks++) {
            uint32_t ah[4], al[4];
            pack_hl(s[2 * ks][0],     s[2 * ks][1],     ah[0], al[0]);
            pack_hl(s[2 * ks][2],     s[2 * ks][3],     ah[1], al[1]);
            pack_hl(s[2 * ks + 1][0], s[2 * ks + 1][1], ah[2], al[2]);
            pack_hl(s[2 * ks + 1][2], s[2 * ks + 1][3], ah[3], al[3]);
#pragma unroll
            for (int nt = 0; nt < 8; nt++) {
                int voff = (ks * 16 + (lane & 15)) * 128 + nt * 16;
                voff ^= (voff >> 3) & 0x70;
                uint32_t vh[2], vl[2];
                ldm_x2t(vh, base + 16384 + voff);
                ldm_x2t(vl, base + 24576 + voff);
                mma16816(o[nt], ah, vh);
                mma16816(o[nt], ah, vl);
                mma16816(o[nt], al, vh);
            }
        }
        __syncthreads();
    }

    float i0 = 1.0f / l0, i1 = 1.0f / l1;
    size_t r0g = qrow0 + w * 16 + quad, r1g = r0g + 8;
#pragma unroll
    for (int nt = 0; nt < 8; nt++) {
        int col = h * 64 + nt * 8 + 2 * pos;
        uint32_t hw, lw;
        pack_hl(o[nt][0] * i0, o[nt][1] * i0, hw, lw);
        ((uint32_t*)Ch_)[(r0g * DM + col) >> 1] = hw;
        ((uint32_t*)Cl_)[(r0g * DM + col) >> 1] = lw;
        pack_hl(o[nt][2] * i1, o[nt][3] * i1, hw, lw);
        ((uint32_t*)Ch_)[(r1g * DM + col) >> 1] = hw;
        ((uint32_t*)Cl_)[(r1g * DM + col) >> 1] = lw;
    }
}

// ---------------- layernorm (biased var), optional bf16 split out ---------
template <int SPLIT>
__global__ __launch_bounds__(256) void layernorm_kernel(
    const float* __restrict__ X, const float* __restrict__ g,
    const float* __restrict__ bt, float* __restrict__ out,
    __nv_bfloat16* __restrict__ Oh, __nv_bfloat16* __restrict__ Ol)
{
    __shared__ float sh_s[8], sh_ss[8], sh_m, sh_r;
    int row = blockIdx.x, tid = threadIdx.x;
    const float* x = X + (size_t)row * DM;
    float4 xv = *(const float4*)&x[tid * 4];
    float s = xv.x + xv.y + xv.z + xv.w;
    float ss = xv.x * xv.x + xv.y * xv.y + xv.z * xv.z + xv.w * xv.w;
#pragma unroll
    for (int off = 16; off; off >>= 1) {
        s += __shfl_xor_sync(0xffffffffu, s, off);
        ss += __shfl_xor_sync(0xffffffffu, ss, off);
    }
    int wid = tid >> 5, lane = tid & 31;
    if (lane == 0) { sh_s[wid] = s; sh_ss[wid] = ss; }
    __syncthreads();
    if (wid == 0) {
        float s2 = (lane < 8) ? sh_s[lane] : 0.0f;
        float ss2 = (lane < 8) ? sh_ss[lane] : 0.0f;
#pragma unroll
        for (int off = 4; off; off >>= 1) {
            s2 += __shfl_xor_sync(0xffffffffu, s2, off);
            ss2 += __shfl_xor_sync(0xffffffffu, ss2, off);
        }
        if (lane == 0) {
            float mean = s2 * (1.0f / DM);
            sh_m = mean;
            sh_r = rsqrtf(ss2 * (1.0f / DM) - mean * mean + 1e-5f);
        }
    }
    __syncthreads();
    float mean = sh_m, rstd = sh_r;
    float4 gv = *(const float4*)&g[tid * 4];
    float4 bv = *(const float4*)&bt[tid * 4];
    float4 ov;
    ov.x = (xv.x - mean) * rstd * gv.x + bv.x;
    ov.y = (xv.y - mean) * rstd * gv.y + bv.y;
    ov.z = (xv.z - mean) * rstd * gv.z + bv.z;
    ov.w = (xv.w - mean) * rstd * gv.w + bv.w;
    *(float4*)&out[(size_t)row * DM + tid * 4] = ov;
    if (SPLIT) {
        uint32_t h0, l0, h1, l1;
        pack_hl(ov.x, ov.y, h0, l0);
        pack_hl(ov.z, ov.w, h1, l1);
        size_t base = ((size_t)row * DM + tid * 4) >> 1;
        ((uint32_t*)Oh)[base] = h0; ((uint32_t*)Oh)[base + 1] = h1;
        ((uint32_t*)Ol)[base] = l0; ((uint32_t*)Ol)[base + 1] = l1;
    }
}

// -------------------------------- host -----------------------------------
extern "C" void kernel_launch(void* const* d_in, const int* in_sizes, int n_in,
                              void* d_out, int out_size)
{
    const float* X = (const float*)d_in[0];
    const unsigned char* mask = (const unsigned char*)d_in[1];
    const float *Wq = (const float*)d_in[2], *bq = (const float*)d_in[3];
    const float *Wk = (const float*)d_in[4], *bk = (const float*)d_in[5];
    const float *Wv = (const float*)d_in[6], *bv = (const float*)d_in[7];
    const float *Wo = (const float*)d_in[8], *bo = (const float*)d_in[9];
    const float *g1 = (const float*)d_in[10], *b1 = (const float*)d_in[11];
    const float *W1 = (const float*)d_in[12], *bf1 = (const float*)d_in[13];
    const float *W2 = (const float*)d_in[14], *bf2 = (const float*)d_in[15];
    const float *g2 = (const float*)d_in[16], *b2 = (const float*)d_in[17];
    float* out = (float*)d_out;

    float *T1p, *AOp;
    cudaGetSymbolAddress((void**)&T1p, g_T1);
    cudaGetSymbolAddress((void**)&AOp, g_AO);
    __nv_bfloat16 *Xh, *Xl, *Qh, *Ql, *Kh, *Kl, *Vh, *Vl, *Ch, *Cl, *AOh, *AOl, *Hh, *Hl, *Wh, *Wl;
    cudaGetSymbolAddress((void**)&Xh, g_Xh);  cudaGetSymbolAddress((void**)&Xl, g_Xl);
    cudaGetSymbolAddress((void**)&Qh, g_Qh);  cudaGetSymbolAddress((void**)&Ql, g_Ql);
    cudaGetSymbolAddress((void**)&Kh, g_Kh);  cudaGetSymbolAddress((void**)&Kl, g_Kl);
    cudaGetSymbolAddress((void**)&Vh, g_Vh);  cudaGetSymbolAddress((void**)&Vl, g_Vl);
    cudaGetSymbolAddress((void**)&Ch, g_Ch);  cudaGetSymbolAddress((void**)&Cl, g_Cl);
    cudaGetSymbolAddress((void**)&AOh, g_AOh); cudaGetSymbolAddress((void**)&AOl, g_AOl);
    cudaGetSymbolAddress((void**)&Hh, g_Hh);  cudaGetSymbolAddress((void**)&Hl, g_Hl);
    cudaGetSymbolAddress((void**)&Wh, g_Wh);  cudaGetSymbolAddress((void**)&Wl, g_Wl);
    unsigned char* MBp;
    cudaGetSymbolAddress((void**)&MBp, g_MB);

    const size_t S1 = (size_t)DM * DM;
    __nv_bfloat16 *qh = Wh, *kh = Wh + S1, *vh = Wh + 2 * S1, *oh = Wh + 3 * S1;
    __nv_bfloat16 *w1h = Wh + 4 * S1, *w2h = Wh + 4 * S1 + (size_t)DM * DFF;
    __nv_bfloat16 *ql = Wl, *kl = Wl + S1, *vl = Wl + 2 * S1, *ol = Wl + 3 * S1;
    __nv_bfloat16 *w1l = Wl + 4 * S1, *w2l = Wl + 4 * S1 + (size_t)DM * DFF;

    cudaFuncSetAttribute(gemm3_kernel<0, 1>, cudaFuncAttributeMaxDynamicSharedMemorySize, SM_TOT);
    cudaFuncSetAttribute(gemm3_kernel<1, 1>, cudaFuncAttributeMaxDynamicSharedMemorySize, SM_TOT);
    cudaFuncSetAttribute(gemm3_kernel<2, 0>, cudaFuncAttributeMaxDynamicSharedMemorySize, SM_TOT);
    cudaFuncSetAttribute(attn_kernel, cudaFuncAttributeMaxDynamicSharedMemorySize, ASM);

    dim3 tb(32, 8);
    splitT_kernel<<<dim3(DM / 32, DM / 32), tb>>>(Wq, qh, ql, DM, DM);
    splitT_kernel<<<dim3(DM / 32, DM / 32), tb>>>(Wk, kh, kl, DM, DM);
    splitT_kernel<<<dim3(DM / 32, DM / 32), tb>>>(Wv, vh, vl, DM, DM);
    splitT_kernel<<<dim3(DM / 32, DM / 32), tb>>>(Wo, oh, ol, DM, DM);
    splitT_kernel<<<dim3(DFF / 32, DM / 32), tb>>>(W1, w1h, w1l, DM, DFF);
    splitT_kernel<<<dim3(DM / 32, DFF / 32), tb>>>(W2, w2h, w2l, DFF, DM);
    maskbits_kernel<<<(BATCH * SEQ * SEQ / 8) / 256, 256>>>(mask, MBp);
    split_kernel<<<(TOKENS * DM) / 1024, 256>>>((const float4*)X, Xh, Xl);

    dim3 gproj(DM / 128, TOKENS / 128), gff1(DFF / 128, TOKENS / 128);

    // QKV projections -> bf16 hi/lo directly
    gemm3_kernel<0, 1><<<gproj, 256, SM_TOT>>>(Xh, Xl, qh, ql, bq, nullptr, nullptr, Qh, Ql, DM, DM);
    gemm3_kernel<0, 1><<<gproj, 256, SM_TOT>>>(Xh, Xl, kh, kl, bk, nullptr, nullptr, Kh, Kl, DM, DM);
    gemm3_kernel<0, 1><<<gproj, 256, SM_TOT>>>(Xh, Xl, vh, vl, bv, nullptr, nullptr, Vh, Vl, DM, DM);

    // attention -> CTX bf16 hi/lo
    dim3 gattn(SEQ / 128, HEADS, BATCH);
    attn_kernel<<<gattn, 256, ASM>>>(Qh, Ql, Kh, Kl, Vh, Vl, MBp, Ch, Cl);

    // Wo + residual(X) -> T1 fp32; LN1 -> AO fp32 + hi/lo
    gemm3_kernel<2, 0><<<gproj, 256, SM_TOT>>>(Ch, Cl, oh, ol, bo, X, T1p, nullptr, nullptr, DM, DM);
    layernorm_kernel<1><<<TOKENS, 256>>>(T1p, g1, b1, AOp, AOh, AOl);

    // FF1 + gelu -> H bf16 hi/lo
    gemm3_kernel<1, 1><<<gff1, 256, SM_TOT>>>(AOh, AOl, w1h, w1l, bf1, nullptr, nullptr, Hh, Hl, DFF, DM);

    // FF2 + residual(AO) -> T1; LN2 -> out
    gemm3_kernel<2, 0><<<gproj, 256, SM_TOT>>>(Hh, Hl, w2h, w2l, bf2, AOp, T1p, nullptr, nullptr, DM, DFF);
    layernorm_kernel<0><<<TOKENS, 256>>>(T1p, g2, b2, out, nullptr, nullptr);
}